// round 2
// baseline (speedup 1.0000x reference)
#include <cuda_runtime.h>
#include <math.h>

#define MAXN 50048
#define MAXE 800000

// ---- scratch (device globals; no allocation allowed) ----
__device__ float g_deg[MAXN];          // degree, then dinv in-place
__device__ int   g_cnt[MAXN];
__device__ int   g_rowptr[MAXN + 1];
__device__ int   g_wtr[MAXN];
__device__ int   g_csrc[MAXE];
__device__ float g_cnorm[MAXE];
__device__ float g_h[(long)MAXN * 128];   // GEMM output (pre-aggregation)
__device__ float g_a[(long)MAXN * 128];   // aggregated output (pre-ReLU)

// ---------------------------------------------------------------------------
// Normalization / CSR build
// ---------------------------------------------------------------------------
__global__ void init_kernel(int n) {
    int i = blockIdx.x * blockDim.x + threadIdx.x;
    if (i < n) { g_deg[i] = 1.0f; g_cnt[i] = 0; }   // self-loop weight 1
}

__global__ void deg_cnt_kernel(const int* __restrict__ dst,
                               const float* __restrict__ ew, int E) {
    int e = blockIdx.x * blockDim.x + threadIdx.x;
    if (e < E) {
        int d = dst[e];
        atomicAdd(&g_deg[d], ew[e]);
        atomicAdd(&g_cnt[d], 1);
    }
}

__global__ void dinv_kernel(int n) {
    int i = blockIdx.x * blockDim.x + threadIdx.x;
    if (i < n) g_deg[i] = rsqrtf(g_deg[i]);   // deg >= 1 always
}

// single-block exclusive scan of g_cnt -> g_rowptr / g_wtr
__global__ void scan_kernel(int n) {
    __shared__ int sh[1024];
    __shared__ int carry;
    int tid = threadIdx.x;
    if (tid == 0) carry = 0;
    __syncthreads();
    for (int base = 0; base < n; base += 1024) {
        int i = base + tid;
        int v = (i < n) ? g_cnt[i] : 0;
        sh[tid] = v;
        __syncthreads();
        #pragma unroll
        for (int off = 1; off < 1024; off <<= 1) {
            int t = (tid >= off) ? sh[tid - off] : 0;
            __syncthreads();
            sh[tid] += t;
            __syncthreads();
        }
        int excl = sh[tid] - v;
        int c = carry;
        if (i < n) { g_rowptr[i] = c + excl; g_wtr[i] = c + excl; }
        __syncthreads();
        if (tid == 0) carry = c + sh[1023];
        __syncthreads();
    }
    if (tid == 0) g_rowptr[n] = carry;
}

__global__ void fill_kernel(const int* __restrict__ src,
                            const int* __restrict__ dst,
                            const float* __restrict__ ew, int E) {
    int e = blockIdx.x * blockDim.x + threadIdx.x;
    if (e < E) {
        int s = src[e], d = dst[e];
        float nm = g_deg[s] * ew[e] * g_deg[d];
        int pos = atomicAdd(&g_wtr[d], 1);
        g_csrc[pos]  = s;
        g_cnorm[pos] = nm;
    }
}

// ---------------------------------------------------------------------------
// SGEMM: C[M,128] = (RELU? relu(A) : A)[M,K] @ B[K,128]
// BM=BN=128, BK=16, 256 threads, 8x8 register tile
// ---------------------------------------------------------------------------
template <bool RELU>
__global__ __launch_bounds__(256)
void gemm_n128(const float* __restrict__ A, const float* __restrict__ B,
               float* __restrict__ C, int M, int K) {
    __shared__ float As[16][128];
    __shared__ float Bs[16][128];
    int tid  = threadIdx.x;
    int row0 = blockIdx.x * 128;
    int tr = tid >> 4, tc = tid & 15;

    float acc[8][8];
    #pragma unroll
    for (int i = 0; i < 8; i++)
        #pragma unroll
        for (int j = 0; j < 8; j++) acc[i][j] = 0.0f;

    for (int kb = 0; kb < K; kb += 16) {
        // A tile: 128 rows x 16 k  (512 float4, 2 per thread), transpose in
        #pragma unroll
        for (int i = 0; i < 2; i++) {
            int f  = tid * 2 + i;
            int r  = f >> 2;
            int kc = (f & 3) * 4;
            float4 v = make_float4(0.f, 0.f, 0.f, 0.f);
            int gr = row0 + r;
            if (gr < M) v = *(const float4*)&A[(long)gr * K + kb + kc];
            if (RELU) {
                v.x = fmaxf(v.x, 0.f); v.y = fmaxf(v.y, 0.f);
                v.z = fmaxf(v.z, 0.f); v.w = fmaxf(v.w, 0.f);
            }
            As[kc + 0][r] = v.x; As[kc + 1][r] = v.y;
            As[kc + 2][r] = v.z; As[kc + 3][r] = v.w;
        }
        // B tile: 16 k-rows x 128 cols
        #pragma unroll
        for (int i = 0; i < 2; i++) {
            int f = tid * 2 + i;
            int r = f >> 5;
            int c = (f & 31) * 4;
            *(float4*)&Bs[r][c] = *(const float4*)&B[(long)(kb + r) * 128 + c];
        }
        __syncthreads();

        #pragma unroll
        for (int k = 0; k < 16; k++) {
            float a[8], b[8];
            #pragma unroll
            for (int i = 0; i < 8; i++) a[i] = As[k][tr * 8 + i];
            #pragma unroll
            for (int j = 0; j < 8; j++) b[j] = Bs[k][tc * 8 + j];
            #pragma unroll
            for (int i = 0; i < 8; i++)
                #pragma unroll
                for (int j = 0; j < 8; j++)
                    acc[i][j] = fmaf(a[i], b[j], acc[i][j]);
        }
        __syncthreads();
    }

    #pragma unroll
    for (int i = 0; i < 8; i++) {
        int gr = row0 + tr * 8 + i;
        if (gr < M) {
            #pragma unroll
            for (int j = 0; j < 8; j += 4) {
                float4 v = make_float4(acc[i][j], acc[i][j+1], acc[i][j+2], acc[i][j+3]);
                *(float4*)&C[(long)gr * 128 + tc * 8 + j] = v;
            }
        }
    }
}

// ---------------------------------------------------------------------------
// Aggregation: out[i,:] = dinv[i]^2 * h[i,:] + bias + sum_{e in CSR[i]} norm_e * h[src_e,:]
// one warp per node, float4 per lane (128 feats)
// ---------------------------------------------------------------------------
__global__ __launch_bounds__(256)
void agg_kernel(const float* __restrict__ h, float* __restrict__ out,
                const float* __restrict__ bias, int n) {
    int node = blockIdx.x * 8 + (threadIdx.x >> 5);
    int lane = threadIdx.x & 31;
    if (node >= n) return;   // whole-warp exit

    float di = g_deg[node];  // holds dinv
    float sl = di * di;
    float4 hv = *(const float4*)&h[(long)node * 128 + lane * 4];
    float4 bv = *(const float4*)&bias[lane * 4];
    float4 acc;
    acc.x = fmaf(sl, hv.x, bv.x);
    acc.y = fmaf(sl, hv.y, bv.y);
    acc.z = fmaf(sl, hv.z, bv.z);
    acc.w = fmaf(sl, hv.w, bv.w);

    int beg = g_rowptr[node], end = g_rowptr[node + 1];
    for (int e = beg; e < end; e += 32) {
        int j = e + lane;
        int   s  = 0;
        float nm = 0.f;
        if (j < end) { s = g_csrc[j]; nm = g_cnorm[j]; }
        int cnt = min(32, end - e);
        for (int t = 0; t < cnt; ++t) {
            int   ss = __shfl_sync(0xffffffff, s,  t);
            float nn = __shfl_sync(0xffffffff, nm, t);
            float4 hs = *(const float4*)&h[(long)ss * 128 + lane * 4];
            acc.x = fmaf(nn, hs.x, acc.x);
            acc.y = fmaf(nn, hs.y, acc.y);
            acc.z = fmaf(nn, hs.z, acc.z);
            acc.w = fmaf(nn, hs.w, acc.w);
        }
    }
    *(float4*)&out[(long)node * 128 + lane * 4] = acc;
}

// ---------------------------------------------------------------------------
// fc + softmax: warp per node. logits = relu(a) @ fc_w + fc_b ; softmax over 10
// ---------------------------------------------------------------------------
__global__ __launch_bounds__(256)
void fc_softmax_kernel(const float* __restrict__ a,
                       const float* __restrict__ fcw,
                       const float* __restrict__ fcb,
                       float* __restrict__ out, int n) {
    int node = blockIdx.x * 8 + (threadIdx.x >> 5);
    int lane = threadIdx.x & 31;
    if (node >= n) return;

    float p[10];
    #pragma unroll
    for (int c = 0; c < 10; c++) p[c] = 0.f;

    #pragma unroll
    for (int kk = 0; kk < 4; kk++) {
        int k = lane + kk * 32;
        float hv = fmaxf(a[(long)node * 128 + k], 0.f);
        #pragma unroll
        for (int c = 0; c < 10; c++)
            p[c] = fmaf(hv, fcw[k * 10 + c], p[c]);
    }
    #pragma unroll
    for (int off = 16; off > 0; off >>= 1)
        #pragma unroll
        for (int c = 0; c < 10; c++)
            p[c] += __shfl_xor_sync(0xffffffff, p[c], off);

    if (lane == 0) {
        float m = -1e30f;
        #pragma unroll
        for (int c = 0; c < 10; c++) { p[c] += fcb[c]; m = fmaxf(m, p[c]); }
        float s = 0.f;
        #pragma unroll
        for (int c = 0; c < 10; c++) { p[c] = expf(p[c] - m); s += p[c]; }
        float inv = 1.0f / s;
        #pragma unroll
        for (int c = 0; c < 10; c++) out[(long)node * 10 + c] = p[c] * inv;
    }
}

// ---------------------------------------------------------------------------
extern "C" void kernel_launch(void* const* d_in, const int* in_sizes, int n_in,
                              void* d_out, int out_size) {
    const float* x   = (const float*)d_in[0];
    const int*   ei  = (const int*)  d_in[1];
    const float* ew  = (const float*)d_in[2];
    const float* W1  = (const float*)d_in[3];
    const float* b1  = (const float*)d_in[4];
    const float* W2  = (const float*)d_in[5];
    const float* b2  = (const float*)d_in[6];
    const float* W3  = (const float*)d_in[7];
    const float* b3  = (const float*)d_in[8];
    const float* fcw = (const float*)d_in[9];
    const float* fcb = (const float*)d_in[10];
    float* out = (float*)d_out;

    int E = in_sizes[2];            // edge_weight count
    int n = in_sizes[0] / 256;      // x is [n, 256]
    const int* src = ei;
    const int* dst = ei + E;

    int nb_n = (n + 255) / 256;
    int nb_e = (E + 255) / 256;
    int nb_g = (n + 127) / 128;     // GEMM blocks (128 rows each)
    int nb_w = (n + 7) / 8;         // warp-per-node kernels (8 warps/block)

    // normalization + CSR (once per launch; layer-invariant)
    init_kernel<<<nb_n, 256>>>(n);
    deg_cnt_kernel<<<nb_e, 256>>>(dst, ew, E);
    dinv_kernel<<<nb_n, 256>>>(n);
    scan_kernel<<<1, 1024>>>(n);
    fill_kernel<<<nb_e, 256>>>(src, dst, ew, E);

    // layer 1: h = x @ W1 ; a = D^-1/2 (A+I) D^-1/2 h + b1
    gemm_n128<false><<<nb_g, 256>>>(x, W1, g_h, n, 256);
    agg_kernel<<<nb_w, 256>>>(g_h, g_a, b1, n);

    // layer 2 (relu applied on GEMM input load)
    gemm_n128<true><<<nb_g, 256>>>(g_a, W2, g_h, n, 128);
    agg_kernel<<<nb_w, 256>>>(g_h, g_a, b2, n);

    // layer 3
    gemm_n128<true><<<nb_g, 256>>>(g_a, W3, g_h, n, 128);
    agg_kernel<<<nb_w, 256>>>(g_h, g_a, b3, n);

    // fc + softmax (relu applied on load)
    fc_softmax_kernel<<<nb_w, 256>>>(g_a, fcw, fcb, out, n);
}

// round 4
// speedup vs baseline: 1.2302x; 1.2302x over previous
#include <cuda_runtime.h>
#include <math.h>

#define MAXN 50048
#define MAXE 800000

// ---- scratch (device globals; no allocation allowed) ----
__device__ float g_deg[MAXN];          // degree, then dinv in-place
__device__ int   g_cnt[MAXN];
__device__ int   g_rowptr[MAXN + 1];
__device__ int   g_wtr[MAXN];
__device__ int   g_csrc[MAXE];
__device__ float g_cnorm[MAXE];
__device__ float g_h[(long)MAXN * 128];   // GEMM output (pre-aggregation)
__device__ float g_a[(long)MAXN * 128];   // aggregated output (post-ReLU)

// ---------------------------------------------------------------------------
// Normalization / CSR build
// ---------------------------------------------------------------------------
__global__ void init_kernel(int n) {
    int i = blockIdx.x * blockDim.x + threadIdx.x;
    if (i < n) { g_deg[i] = 1.0f; g_cnt[i] = 0; }   // self-loop weight 1
}

__global__ void deg_cnt_kernel(const int* __restrict__ dst,
                               const float* __restrict__ ew, int E) {
    int e = blockIdx.x * blockDim.x + threadIdx.x;
    if (e < E) {
        int d = dst[e];
        atomicAdd(&g_deg[d], ew[e]);
        atomicAdd(&g_cnt[d], 1);
    }
}

__global__ void dinv_kernel(int n) {
    int i = blockIdx.x * blockDim.x + threadIdx.x;
    if (i < n) g_deg[i] = rsqrtf(g_deg[i]);   // deg >= 1 always
}

// single-block scan: thread-sequential partials + hierarchical block scan
__global__ void scan_kernel(int n) {
    const int T = 1024;
    int tid = threadIdx.x;
    int per = (n + T - 1) / T;
    int b0 = tid * per;
    int b1 = min(b0 + per, n);
    if (b1 < b0) b1 = b0;

    int sum = 0;
    for (int i = b0; i < b1; i++) sum += g_cnt[i];

    // block-wide inclusive scan of per-thread sums
    int lane = tid & 31, wid = tid >> 5;
    unsigned full = 0xffffffffu;
    int v = sum;
    #pragma unroll
    for (int off = 1; off < 32; off <<= 1) {
        int t = __shfl_up_sync(full, v, off);
        if (lane >= off) v += t;
    }
    __shared__ int wsum[32];
    if (lane == 31) wsum[wid] = v;
    __syncthreads();
    if (wid == 0) {
        int w = wsum[lane];
        #pragma unroll
        for (int off = 1; off < 32; off <<= 1) {
            int t = __shfl_up_sync(full, w, off);
            if (lane >= off) w += t;
        }
        wsum[lane] = w;
    }
    __syncthreads();
    int excl = v - sum + (wid > 0 ? wsum[wid - 1] : 0);

    int run = excl;
    for (int i = b0; i < b1; i++) {
        g_rowptr[i] = run;
        g_wtr[i]    = run;
        run += g_cnt[i];
    }
    if (tid == T - 1) g_rowptr[n] = run;
}

__global__ void fill_kernel(const int* __restrict__ src,
                            const int* __restrict__ dst,
                            const float* __restrict__ ew, int E) {
    int e = blockIdx.x * blockDim.x + threadIdx.x;
    if (e < E) {
        int s = src[e], d = dst[e];
        float nm = g_deg[s] * ew[e] * g_deg[d];
        int pos = atomicAdd(&g_wtr[d], 1);
        g_csrc[pos]  = s;
        g_cnorm[pos] = nm;
    }
}

// ---------------------------------------------------------------------------
// SGEMM: C[M,128] = A[M,K] @ B[K,128]
// 128x128 tile, 256 threads, 8x8 per thread (split rows/cols: r, r+64)
// As[row][k] 17-pad (broadcast scalar reads); Bs[k][col] float4 conflict-free
// ---------------------------------------------------------------------------
__global__ __launch_bounds__(256)
void gemm_n128(const float* __restrict__ A, const float* __restrict__ B,
               float* __restrict__ C, int M, int K) {
    __shared__ float As[128][17];
    __shared__ float Bs[16][128];
    int tid  = threadIdx.x;
    int row0 = blockIdx.x * 128;
    int tx = tid & 15;          // column group
    int ty = tid >> 4;          // row group

    float acc[8][8];
    #pragma unroll
    for (int i = 0; i < 8; i++)
        #pragma unroll
        for (int j = 0; j < 8; j++) acc[i][j] = 0.0f;

    for (int kb = 0; kb < K; kb += 16) {
        // A tile: 128 rows x 16 k (512 float4, 2 per thread)
        #pragma unroll
        for (int i = 0; i < 2; i++) {
            int f  = tid * 2 + i;
            int r  = f >> 2;
            int kc = (f & 3) * 4;
            float4 v = make_float4(0.f, 0.f, 0.f, 0.f);
            int gr = row0 + r;
            if (gr < M) v = *(const float4*)&A[(size_t)gr * K + kb + kc];
            As[r][kc + 0] = v.x; As[r][kc + 1] = v.y;
            As[r][kc + 2] = v.z; As[r][kc + 3] = v.w;
        }
        // B tile: 16 k-rows x 128 cols (float4, conflict-free)
        #pragma unroll
        for (int i = 0; i < 2; i++) {
            int f = tid * 2 + i;
            int r = f >> 5;
            int c = (f & 31) * 4;
            *(float4*)&Bs[r][c] = *(const float4*)&B[(size_t)(kb + r) * 128 + c];
        }
        __syncthreads();

        #pragma unroll
        for (int k = 0; k < 16; k++) {
            float a[8];
            #pragma unroll
            for (int i = 0; i < 4; i++) {
                a[i]     = As[ty * 4 + i][k];        // broadcast (2 addrs/warp)
                a[i + 4] = As[64 + ty * 4 + i][k];
            }
            float4 b0 = *(const float4*)&Bs[k][tx * 4];       // conflict-free
            float4 b1 = *(const float4*)&Bs[k][64 + tx * 4];
            float b[8] = {b0.x, b0.y, b0.z, b0.w, b1.x, b1.y, b1.z, b1.w};
            #pragma unroll
            for (int i = 0; i < 8; i++)
                #pragma unroll
                for (int j = 0; j < 8; j++)
                    acc[i][j] = fmaf(a[i], b[j], acc[i][j]);
        }
        __syncthreads();
    }

    #pragma unroll
    for (int half = 0; half < 2; half++) {
        #pragma unroll
        for (int i = 0; i < 4; i++) {
            int gr = row0 + half * 64 + ty * 4 + i;
            if (gr < M) {
                float4 v0 = make_float4(acc[half*4+i][0], acc[half*4+i][1],
                                        acc[half*4+i][2], acc[half*4+i][3]);
                float4 v1 = make_float4(acc[half*4+i][4], acc[half*4+i][5],
                                        acc[half*4+i][6], acc[half*4+i][7]);
                *(float4*)&C[(size_t)gr * 128 + tx * 4]      = v0;
                *(float4*)&C[(size_t)gr * 128 + 64 + tx * 4] = v1;
            }
        }
    }
}

// ---------------------------------------------------------------------------
// Aggregation (+bias, +ReLU on store): warp per node, 4-deep pipelined gather
// ---------------------------------------------------------------------------
__global__ __launch_bounds__(256)
void agg_relu_kernel(const float* __restrict__ h, float* __restrict__ out,
                     const float* __restrict__ bias, int n) {
    int node = blockIdx.x * 8 + (threadIdx.x >> 5);
    int lane = threadIdx.x & 31;
    if (node >= n) return;   // whole-warp exit (n % 8 handled by grid)

    int off = lane * 4;
    float di = g_deg[node];
    float sl = di * di;
    float4 hv = *(const float4*)(h + (size_t)node * 128 + off);
    float4 bv = *(const float4*)(bias + off);
    float4 acc;
    acc.x = fmaf(sl, hv.x, bv.x);
    acc.y = fmaf(sl, hv.y, bv.y);
    acc.z = fmaf(sl, hv.z, bv.z);
    acc.w = fmaf(sl, hv.w, bv.w);

    int e   = g_rowptr[node];
    int end = g_rowptr[node + 1];
    for (; e + 4 <= end; e += 4) {
        int   s0 = g_csrc[e],     s1 = g_csrc[e + 1];
        int   s2 = g_csrc[e + 2], s3 = g_csrc[e + 3];
        float w0 = g_cnorm[e],     w1 = g_cnorm[e + 1];
        float w2 = g_cnorm[e + 2], w3 = g_cnorm[e + 3];
        float4 v0 = *(const float4*)(h + (size_t)s0 * 128 + off);
        float4 v1 = *(const float4*)(h + (size_t)s1 * 128 + off);
        float4 v2 = *(const float4*)(h + (size_t)s2 * 128 + off);
        float4 v3 = *(const float4*)(h + (size_t)s3 * 128 + off);
        acc.x = fmaf(w0, v0.x, acc.x); acc.y = fmaf(w0, v0.y, acc.y);
        acc.z = fmaf(w0, v0.z, acc.z); acc.w = fmaf(w0, v0.w, acc.w);
        acc.x = fmaf(w1, v1.x, acc.x); acc.y = fmaf(w1, v1.y, acc.y);
        acc.z = fmaf(w1, v1.z, acc.z); acc.w = fmaf(w1, v1.w, acc.w);
        acc.x = fmaf(w2, v2.x, acc.x); acc.y = fmaf(w2, v2.y, acc.y);
        acc.z = fmaf(w2, v2.z, acc.z); acc.w = fmaf(w2, v2.w, acc.w);
        acc.x = fmaf(w3, v3.x, acc.x); acc.y = fmaf(w3, v3.y, acc.y);
        acc.z = fmaf(w3, v3.z, acc.z); acc.w = fmaf(w3, v3.w, acc.w);
    }
    for (; e < end; e++) {
        int   s = g_csrc[e];
        float w = g_cnorm[e];
        float4 v = *(const float4*)(h + (size_t)s * 128 + off);
        acc.x = fmaf(w, v.x, acc.x); acc.y = fmaf(w, v.y, acc.y);
        acc.z = fmaf(w, v.z, acc.z); acc.w = fmaf(w, v.w, acc.w);
    }

    acc.x = fmaxf(acc.x, 0.f); acc.y = fmaxf(acc.y, 0.f);
    acc.z = fmaxf(acc.z, 0.f); acc.w = fmaxf(acc.w, 0.f);
    *(float4*)(out + (size_t)node * 128 + off) = acc;
}

// ---------------------------------------------------------------------------
// Fused: layer-3 aggregation + bias + ReLU + fc (128->10) + softmax
// ---------------------------------------------------------------------------
__global__ __launch_bounds__(256)
void agg_fc_softmax_kernel(const float* __restrict__ h,
                           const float* __restrict__ bias,
                           const float* __restrict__ fcw,
                           const float* __restrict__ fcb,
                           float* __restrict__ out, int n) {
    __shared__ float wsh[128 * 10];
    for (int i = threadIdx.x; i < 1280; i += 256) wsh[i] = fcw[i];
    __syncthreads();

    int node = blockIdx.x * 8 + (threadIdx.x >> 5);
    int lane = threadIdx.x & 31;
    if (node >= n) return;

    int off = lane * 4;
    float di = g_deg[node];
    float sl = di * di;
    float4 hv = *(const float4*)(h + (size_t)node * 128 + off);
    float4 bv = *(const float4*)(bias + off);
    float4 acc;
    acc.x = fmaf(sl, hv.x, bv.x);
    acc.y = fmaf(sl, hv.y, bv.y);
    acc.z = fmaf(sl, hv.z, bv.z);
    acc.w = fmaf(sl, hv.w, bv.w);

    int e   = g_rowptr[node];
    int end = g_rowptr[node + 1];
    for (; e + 4 <= end; e += 4) {
        int   s0 = g_csrc[e],     s1 = g_csrc[e + 1];
        int   s2 = g_csrc[e + 2], s3 = g_csrc[e + 3];
        float w0 = g_cnorm[e],     w1 = g_cnorm[e + 1];
        float w2 = g_cnorm[e + 2], w3 = g_cnorm[e + 3];
        float4 v0 = *(const float4*)(h + (size_t)s0 * 128 + off);
        float4 v1 = *(const float4*)(h + (size_t)s1 * 128 + off);
        float4 v2 = *(const float4*)(h + (size_t)s2 * 128 + off);
        float4 v3 = *(const float4*)(h + (size_t)s3 * 128 + off);
        acc.x = fmaf(w0, v0.x, acc.x); acc.y = fmaf(w0, v0.y, acc.y);
        acc.z = fmaf(w0, v0.z, acc.z); acc.w = fmaf(w0, v0.w, acc.w);
        acc.x = fmaf(w1, v1.x, acc.x); acc.y = fmaf(w1, v1.y, acc.y);
        acc.z = fmaf(w1, v1.z, acc.z); acc.w = fmaf(w1, v1.w, acc.w);
        acc.x = fmaf(w2, v2.x, acc.x); acc.y = fmaf(w2, v2.y, acc.y);
        acc.z = fmaf(w2, v2.z, acc.z); acc.w = fmaf(w2, v2.w, acc.w);
        acc.x = fmaf(w3, v3.x, acc.x); acc.y = fmaf(w3, v3.y, acc.y);
        acc.z = fmaf(w3, v3.z, acc.z); acc.w = fmaf(w3, v3.w, acc.w);
    }
    for (; e < end; e++) {
        int   s = g_csrc[e];
        float w = g_cnorm[e];
        float4 v = *(const float4*)(h + (size_t)s * 128 + off);
        acc.x = fmaf(w, v.x, acc.x); acc.y = fmaf(w, v.y, acc.y);
        acc.z = fmaf(w, v.z, acc.z); acc.w = fmaf(w, v.w, acc.w);
    }

    float f0 = fmaxf(acc.x, 0.f), f1 = fmaxf(acc.y, 0.f);
    float f2 = fmaxf(acc.z, 0.f), f3 = fmaxf(acc.w, 0.f);

    float p[10];
    #pragma unroll
    for (int c = 0; c < 10; c++) {
        p[c] = f0 * wsh[(off + 0) * 10 + c]
             + f1 * wsh[(off + 1) * 10 + c]
             + f2 * wsh[(off + 2) * 10 + c]
             + f3 * wsh[(off + 3) * 10 + c];
    }
    #pragma unroll
    for (int s = 16; s > 0; s >>= 1)
        #pragma unroll
        for (int c = 0; c < 10; c++)
            p[c] += __shfl_xor_sync(0xffffffffu, p[c], s);

    if (lane == 0) {
        float m = -1e30f;
        #pragma unroll
        for (int c = 0; c < 10; c++) { p[c] += fcb[c]; m = fmaxf(m, p[c]); }
        float sum = 0.f;
        #pragma unroll
        for (int c = 0; c < 10; c++) { p[c] = __expf(p[c] - m); sum += p[c]; }
        float inv = 1.0f / sum;
        #pragma unroll
        for (int c = 0; c < 10; c++) out[(size_t)node * 10 + c] = p[c] * inv;
    }
}

// ---------------------------------------------------------------------------
extern "C" void kernel_launch(void* const* d_in, const int* in_sizes, int n_in,
                              void* d_out, int out_size) {
    const float* x   = (const float*)d_in[0];
    const int*   ei  = (const int*)  d_in[1];
    const float* ew  = (const float*)d_in[2];
    const float* W1  = (const float*)d_in[3];
    const float* b1  = (const float*)d_in[4];
    const float* W2  = (const float*)d_in[5];
    const float* b2  = (const float*)d_in[6];
    const float* W3  = (const float*)d_in[7];
    const float* b3  = (const float*)d_in[8];
    const float* fcw = (const float*)d_in[9];
    const float* fcb = (const float*)d_in[10];
    float* out = (float*)d_out;

    int E = in_sizes[2];            // edge_weight count
    int n = in_sizes[0] / 256;      // x is [n, 256]
    const int* src = ei;
    const int* dst = ei + E;

    int nb_n = (n + 255) / 256;
    int nb_e = (E + 255) / 256;
    int nb_g = (n + 127) / 128;     // GEMM blocks (128 rows each)
    int nb_w = (n + 7) / 8;         // warp-per-node kernels (8 warps/block)

    // normalization + CSR (once per launch; layer-invariant)
    init_kernel<<<nb_n, 256>>>(n);
    deg_cnt_kernel<<<nb_e, 256>>>(dst, ew, E);
    dinv_kernel<<<nb_n, 256>>>(n);
    scan_kernel<<<1, 1024>>>(n);
    fill_kernel<<<nb_e, 256>>>(src, dst, ew, E);

    // layer 1
    gemm_n128<<<nb_g, 256>>>(x, W1, g_h, n, 256);
    agg_relu_kernel<<<nb_w, 256>>>(g_h, g_a, b1, n);

    // layer 2 (g_a already ReLU'd)
    gemm_n128<<<nb_g, 256>>>(g_a, W2, g_h, n, 128);
    agg_relu_kernel<<<nb_w, 256>>>(g_h, g_a, b2, n);

    // layer 3: gemm, then fused agg + fc + softmax
    gemm_n128<<<nb_g, 256>>>(g_a, W3, g_h, n, 128);
    agg_fc_softmax_kernel<<<nb_w, 256>>>(g_h, b3, fcw, fcb, out, n);
}